// round 3
// baseline (speedup 1.0000x reference)
#include <cuda_runtime.h>
#include <math.h>

#define EMB   512
#define HDIM  512
#define SEQ   2048
#define NENT  256
#define KTOK  8
#define G4H   2048   // 4*HDIM

#define NCTA  64     // CTAs per direction in the recurrence kernel
#define JPC   8      // h-indices owned per CTA

// ---------------- scratch (device globals; no allocation allowed) ----------
__device__ float g_xproj[2][SEQ][G4H];        // 32 MB: x @ W_ih.T + b
__device__ float g_h[2][SEQ][HDIM];           // 8 MB: contiguous h history (entity kernel)
// tagged h-slice packets: 3 x float4 per (dir, t, cta); 4th lane of each = epoch tag
__device__ __align__(128) float4 g_slots[2][SEQ][NCTA][4];   // 16 MB (4th float4 = pad)
__device__ int g_epoch;                        // bumped once per launch

__device__ __forceinline__ float fast_sigmoid(float x) {
    return __fdividef(1.f, 1.f + __expf(-x));
}
__device__ __forceinline__ float fast_tanh(float x) {
    return __fdividef(2.f, 1.f + __expf(-2.f * x)) - 1.f;
}

// ===========================================================================
// Kernel 1: fused embedding gather + x_proj GEMM (+bias), both directions.
// ===========================================================================
__global__ __launch_bounds__(256) void xproj_kernel(
    const float* __restrict__ emb_table,
    const int*   __restrict__ token_ids,
    const float* __restrict__ W_ih_f, const float* __restrict__ b_f,
    const float* __restrict__ W_ih_b, const float* __restrict__ b_b)
{
    __shared__ int   tok[64];
    __shared__ float As[16][68];
    __shared__ float Bs[16][68];

    const int tid = threadIdx.x;
    const int t0  = blockIdx.x * 64;
    const int r0  = blockIdx.y * 64;
    const int d   = blockIdx.z;

    // bump the epoch once per launch (visible to lstm_kernel via launch ordering)
    if (blockIdx.x == 0 && blockIdx.y == 0 && blockIdx.z == 0 && tid == 0)
        g_epoch = g_epoch + 1;

    if (tid < 64) tok[tid] = token_ids[t0 + tid];
    __syncthreads();

    const float* __restrict__ Wih  = d ? W_ih_b : W_ih_f;
    const float* __restrict__ bias = d ? b_b    : b_f;

    float acc[4][4];
    #pragma unroll
    for (int i = 0; i < 4; i++)
        #pragma unroll
        for (int j = 0; j < 4; j++) acc[i][j] = 0.f;

    const int lrow = tid >> 2;
    const int e4   = tid & 3;
    const int tx   = tid & 15;
    const int ty   = tid >> 4;

    const size_t arow = (size_t)tok[lrow] * EMB;
    const size_t brow = (size_t)(r0 + lrow) * EMB;

    for (int k0 = 0; k0 < EMB; k0 += 16) {
        float4 av = *(const float4*)(emb_table + arow + k0 + e4 * 4);
        float4 bv = *(const float4*)(Wih       + brow + k0 + e4 * 4);
        __syncthreads();
        As[e4 * 4 + 0][lrow] = av.x; As[e4 * 4 + 1][lrow] = av.y;
        As[e4 * 4 + 2][lrow] = av.z; As[e4 * 4 + 3][lrow] = av.w;
        Bs[e4 * 4 + 0][lrow] = bv.x; Bs[e4 * 4 + 1][lrow] = bv.y;
        Bs[e4 * 4 + 2][lrow] = bv.z; Bs[e4 * 4 + 3][lrow] = bv.w;
        __syncthreads();
        #pragma unroll
        for (int kk = 0; kk < 16; kk++) {
            float4 a = *(const float4*)&As[kk][tx * 4];
            float4 b = *(const float4*)&Bs[kk][ty * 4];
            acc[0][0] = fmaf(a.x, b.x, acc[0][0]); acc[0][1] = fmaf(a.x, b.y, acc[0][1]);
            acc[0][2] = fmaf(a.x, b.z, acc[0][2]); acc[0][3] = fmaf(a.x, b.w, acc[0][3]);
            acc[1][0] = fmaf(a.y, b.x, acc[1][0]); acc[1][1] = fmaf(a.y, b.y, acc[1][1]);
            acc[1][2] = fmaf(a.y, b.z, acc[1][2]); acc[1][3] = fmaf(a.y, b.w, acc[1][3]);
            acc[2][0] = fmaf(a.z, b.x, acc[2][0]); acc[2][1] = fmaf(a.z, b.y, acc[2][1]);
            acc[2][2] = fmaf(a.z, b.z, acc[2][2]); acc[2][3] = fmaf(a.z, b.w, acc[2][3]);
            acc[3][0] = fmaf(a.w, b.x, acc[3][0]); acc[3][1] = fmaf(a.w, b.y, acc[3][1]);
            acc[3][2] = fmaf(a.w, b.z, acc[3][2]); acc[3][3] = fmaf(a.w, b.w, acc[3][3]);
        }
    }

    float4 b4 = *(const float4*)(bias + r0 + ty * 4);
    #pragma unroll
    for (int i = 0; i < 4; i++) {
        int t = t0 + tx * 4 + i;
        float4 o = make_float4(acc[i][0] + b4.x, acc[i][1] + b4.y,
                               acc[i][2] + b4.z, acc[i][3] + b4.w);
        *(float4*)&g_xproj[d][t][r0 + ty * 4] = o;
    }
}

// ===========================================================================
// Kernel 2: persistent bi-LSTM recurrence, 128 co-resident CTAs.
// Exchange medium: self-tagged 16B packets (tag = launch epoch in lane 3).
// No atomics, no separate flags: a successful poll delivers the data.
// ===========================================================================
__global__ __launch_bounds__(256) void lstm_kernel(
    const float* __restrict__ W_hh_f,
    const float* __restrict__ W_hh_b)
{
    const int tid = threadIdx.x;
    const int bx  = blockIdx.x;
    const int d   = bx >> 6;
    const int cb  = bx & 63;
    const int j0  = cb * JPC;

    const float* __restrict__ Whh = d ? W_hh_b : W_hh_f;

    const int r  = tid >> 3;        // local row 0..31 (= gate*8 + jj)
    const int cg = tid & 7;         // column group (64 cols)
    const int q  = r >> 3;
    const int jj = r & 7;
    const int grow = q * HDIM + j0 + jj;

    const float4* wp = (const float4*)(Whh + (size_t)grow * HDIM + cg * 64);
    float4 w[16];
    #pragma unroll
    for (int i = 0; i < 16; i++) w[i] = wp[i];

    const int epoch  = g_epoch;
    const float tagf = __int_as_float(epoch);

    // h in smem with 68-float pitch per 64-col chunk (kills the cg bank alias)
    __shared__ float hsm[8 * 68];
    __shared__ float gacc[32];

    float c = 0.f;

    #pragma unroll 1
    for (int step = 0; step < SEQ; step++) {
        const int t = d ? (SEQ - 1 - step) : step;

        // gate-input prefetch (warp 0 lanes 0..7); latency hides under poll+GEMV
        float xp0 = 0.f, xp1 = 0.f, xp2 = 0.f, xp3 = 0.f;
        if (tid < 8) {
            const float* xr = &g_xproj[d][t][0];
            xp0 = __ldg(xr + 0 * HDIM + j0 + tid);
            xp1 = __ldg(xr + 1 * HDIM + j0 + tid);
            xp2 = __ldg(xr + 2 * HDIM + j0 + tid);
            xp3 = __ldg(xr + 3 * HDIM + j0 + tid);
        }

        if (step == 0) {
            for (int i = tid; i < 8 * 68; i += 256) hsm[i] = 0.f;
        } else if (tid >= 64 && tid < 128) {
            // poller warps (2,3): one slot each; poll = data delivery
            const int s = tid - 64;
            const int tprev = d ? (t + 1) : (t - 1);
            const float4* base = &g_slots[d][tprev][s][0];
            float4 A, B, C;
            do {
                asm volatile("ld.volatile.global.v4.f32 {%0,%1,%2,%3}, [%4];"
                             : "=f"(A.x), "=f"(A.y), "=f"(A.z), "=f"(A.w)
                             : "l"(base) : "memory");
                asm volatile("ld.volatile.global.v4.f32 {%0,%1,%2,%3}, [%4];"
                             : "=f"(B.x), "=f"(B.y), "=f"(B.z), "=f"(B.w)
                             : "l"(base + 1) : "memory");
                asm volatile("ld.volatile.global.v4.f32 {%0,%1,%2,%3}, [%4];"
                             : "=f"(C.x), "=f"(C.y), "=f"(C.z), "=f"(C.w)
                             : "l"(base + 2) : "memory");
            } while (__float_as_int(A.w) != epoch ||
                     __float_as_int(B.w) != epoch ||
                     __float_as_int(C.w) != epoch);
            // scatter 8 floats into the pitched hsm: chunk = s>>3, offset (s&7)*8
            float* hb = &hsm[(s >> 3) * 68 + (s & 7) * 8];
            ((float4*)hb)[0] = make_float4(A.x, A.y, A.z, B.x);
            ((float4*)hb)[1] = make_float4(B.y, B.z, C.x, C.y);
        }
        __syncthreads();   // S1: hsm ready

        // GEMV slice: row r over cols [cg*64, cg*64+64), pitched smem
        float a = 0.f;
        const float4* h4 = (const float4*)&hsm[cg * 68];
        #pragma unroll
        for (int i = 0; i < 16; i++) {
            float4 hv = h4[i];
            a = fmaf(w[i].x, hv.x, a);
            a = fmaf(w[i].y, hv.y, a);
            a = fmaf(w[i].z, hv.z, a);
            a = fmaf(w[i].w, hv.w, a);
        }
        a += __shfl_xor_sync(0xffffffffu, a, 4);
        a += __shfl_xor_sync(0xffffffffu, a, 2);
        a += __shfl_xor_sync(0xffffffffu, a, 1);
        if (cg == 0) gacc[r] = a;
        __syncthreads();   // S2: gacc ready (also: all hsm reads done)

        // gates on warp 0 lanes 0..7; pollers (warps 2,3) run ahead to next poll
        if (tid < 8) {
            float gi = xp0 + gacc[0 * 8 + tid];
            float gf = xp1 + gacc[1 * 8 + tid];
            float gg = xp2 + gacc[2 * 8 + tid];
            float go = xp3 + gacc[3 * 8 + tid];
            float ig = fast_sigmoid(gi);
            float fg = fast_sigmoid(gf);
            float og = fast_sigmoid(go);
            c = fg * c + ig * fast_tanh(gg);
            float hv = og * fast_tanh(c);

            // gather the 8 h values into lane 0 and publish tagged packets
            float h0 = __shfl_sync(0xffu, hv, 0);
            float h1 = __shfl_sync(0xffu, hv, 1);
            float h2 = __shfl_sync(0xffu, hv, 2);
            float h3 = __shfl_sync(0xffu, hv, 3);
            float h4v = __shfl_sync(0xffu, hv, 4);
            float h5 = __shfl_sync(0xffu, hv, 5);
            float h6 = __shfl_sync(0xffu, hv, 6);
            float h7 = __shfl_sync(0xffu, hv, 7);
            if (tid == 0) {
                float4* slot = &g_slots[d][t][cb][0];
                asm volatile("st.volatile.global.v4.f32 [%0], {%1,%2,%3,%4};"
                             :: "l"(slot + 0), "f"(h0), "f"(h1), "f"(h2), "f"(tagf) : "memory");
                asm volatile("st.volatile.global.v4.f32 [%0], {%1,%2,%3,%4};"
                             :: "l"(slot + 1), "f"(h3), "f"(h4v), "f"(h5), "f"(tagf) : "memory");
                asm volatile("st.volatile.global.v4.f32 [%0], {%1,%2,%3,%4};"
                             :: "l"(slot + 2), "f"(h6), "f"(h7), "f"(0.f), "f"(tagf) : "memory");
                // contiguous copy for the entity kernel (off the critical path)
                float4* hrow = (float4*)&g_h[d][t][j0];
                hrow[0] = make_float4(h0, h1, h2, h3);
                hrow[1] = make_float4(h4v, h5, h6, h7);
            }
        }
        // no barrier needed here: next-step hsm writes happen only after the
        // pollers' tag match, which requires this step's publish anyway.
    }
}

// ===========================================================================
// Kernel 3: per-entity attention pool (entity_seg == repeat(arange(256), 8)).
// ===========================================================================
__global__ __launch_bounds__(256) void entity_kernel(
    const float* __restrict__ w_attn,
    const float* __restrict__ b_attn,
    const int*   __restrict__ entity_pos,
    float*       __restrict__ out)
{
    __shared__ int   pos[8];
    __shared__ float ssm[8];
    __shared__ float wsm[8];

    const int e   = blockIdx.x;
    const int tid = threadIdx.x;

    if (tid < 8) pos[tid] = entity_pos[e * KTOK + tid];
    __syncthreads();

    const int warp = tid >> 5, lane = tid & 31;
    const int p = pos[warp];
    float a = 0.f;
    for (int cc = lane; cc < HDIM; cc += 32)
        a = fmaf(g_h[0][p][cc], w_attn[cc], a);
    for (int cc = lane; cc < HDIM; cc += 32)
        a = fmaf(g_h[1][p][cc], w_attn[HDIM + cc], a);
    #pragma unroll
    for (int o = 16; o > 0; o >>= 1) a += __shfl_xor_sync(0xffffffffu, a, o);
    if (lane == 0) ssm[warp] = a + b_attn[0];
    __syncthreads();

    if (tid == 0) {
        float m = ssm[0];
        #pragma unroll
        for (int k = 1; k < 8; k++) m = fmaxf(m, ssm[k]);
        float ex[8], den = 0.f;
        #pragma unroll
        for (int k = 0; k < 8; k++) { ex[k] = expf(ssm[k] - m); den += ex[k]; }
        #pragma unroll
        for (int k = 0; k < 8; k++) wsm[k] = ex[k] / den;
    }
    __syncthreads();

    const int half = tid >> 7;
    const int c4   = tid & 127;
    float4 acc = make_float4(0.f, 0.f, 0.f, 0.f);
    #pragma unroll
    for (int k = 0; k < 8; k++) {
        float wk = wsm[k];
        float4 v = ((const float4*)&g_h[half][pos[k]][0])[c4];
        acc.x = fmaf(wk, v.x, acc.x);
        acc.y = fmaf(wk, v.y, acc.y);
        acc.z = fmaf(wk, v.z, acc.z);
        acc.w = fmaf(wk, v.w, acc.w);
    }
    ((float4*)(out + (size_t)e * (2 * HDIM) + half * HDIM))[c4] = acc;
}

// ===========================================================================
extern "C" void kernel_launch(void* const* d_in, const int* in_sizes, int n_in,
                              void* d_out, int out_size)
{
    const float* emb_table  = (const float*)d_in[0];
    const float* W_ih_f     = (const float*)d_in[1];
    const float* W_hh_f     = (const float*)d_in[2];
    const float* b_f        = (const float*)d_in[3];
    const float* W_ih_b     = (const float*)d_in[4];
    const float* W_hh_b     = (const float*)d_in[5];
    const float* b_b        = (const float*)d_in[6];
    const float* w_attn     = (const float*)d_in[7];
    const float* b_attn     = (const float*)d_in[8];
    const int*   token_ids  = (const int*)d_in[9];
    const int*   entity_pos = (const int*)d_in[10];
    // d_in[11] entity_seg: repeat(arange(NENT), KTOK) -> implicit

    xproj_kernel<<<dim3(32, 32, 2), 256>>>(emb_table, token_ids,
                                           W_ih_f, b_f, W_ih_b, b_b);
    lstm_kernel<<<2 * NCTA, 256>>>(W_hh_f, W_hh_b);
    entity_kernel<<<NENT, 256>>>(w_attn, b_attn, entity_pos, (float*)d_out);
}

// round 6
// speedup vs baseline: 1.6178x; 1.6178x over previous
#include <cuda_runtime.h>
#include <math.h>

#define EMB   512
#define HDIM  512
#define SEQ   2048
#define NENT  256
#define KTOK  8
#define G4H   2048   // 4*HDIM

#define NCTA  64     // CTAs per direction in the recurrence kernel
#define JPC   8      // h-indices owned per CTA

#define SENTINEL_U 0x7F800001u   // signaling-NaN pattern; h is never NaN

// ---------------- scratch (device globals; no allocation allowed) ----------
__device__ float g_xproj[2][SEQ][G4H];   // 32 MB: x @ W_ih.T + b
// h history AND exchange medium: [d][t] is 512 contiguous floats (h order),
// published as sector-atomic 16B packets, validity = lane.x != SENTINEL.
__device__ __align__(128) float4 g_slots[2][SEQ][NCTA][2];   // 8 MB

__device__ __forceinline__ float fast_sigmoid(float x) {
    return __fdividef(1.f, 1.f + __expf(-x));
}
__device__ __forceinline__ float fast_tanh(float x) {
    return __fdividef(2.f, 1.f + __expf(-2.f * x)) - 1.f;
}

// ===========================================================================
// Kernel 1: fused embedding gather + x_proj GEMM (+bias), both directions.
// Also sentinel-clears ALL of g_slots (512 blocks x 256 threads x 4 float4
// = 524288 float4 = the whole array; R4 bug: only half was cleared).
// ===========================================================================
__global__ __launch_bounds__(256) void xproj_kernel(
    const float* __restrict__ emb_table,
    const int*   __restrict__ token_ids,
    const float* __restrict__ W_ih_f, const float* __restrict__ b_f,
    const float* __restrict__ W_ih_b, const float* __restrict__ b_b)
{
    __shared__ int   tok[64];
    __shared__ float As[16][68];
    __shared__ float Bs[16][68];

    const int tid = threadIdx.x;
    const int t0  = blockIdx.x * 64;
    const int r0  = blockIdx.y * 64;
    const int d   = blockIdx.z;

    // sentinel-clear the FULL g_slots array
    if (blockIdx.z == 0 && blockIdx.y < 16) {
        const float s = __uint_as_float(SENTINEL_U);
        float4 sv = make_float4(s, s, s, s);
        size_t lin = ((size_t)(blockIdx.y * 32 + blockIdx.x) * 256 + tid) * 4;
        float4* flat = &g_slots[0][0][0][0];
        flat[lin]     = sv;
        flat[lin + 1] = sv;
        flat[lin + 2] = sv;
        flat[lin + 3] = sv;
    }

    if (tid < 64) tok[tid] = token_ids[t0 + tid];
    __syncthreads();

    const float* __restrict__ Wih  = d ? W_ih_b : W_ih_f;
    const float* __restrict__ bias = d ? b_b    : b_f;

    float acc[4][4];
    #pragma unroll
    for (int i = 0; i < 4; i++)
        #pragma unroll
        for (int j = 0; j < 4; j++) acc[i][j] = 0.f;

    const int lrow = tid >> 2;
    const int e4   = tid & 3;
    const int tx   = tid & 15;
    const int ty   = tid >> 4;

    const size_t arow = (size_t)tok[lrow] * EMB;
    const size_t brow = (size_t)(r0 + lrow) * EMB;

    for (int k0 = 0; k0 < EMB; k0 += 16) {
        float4 av = *(const float4*)(emb_table + arow + k0 + e4 * 4);
        float4 bv = *(const float4*)(Wih       + brow + k0 + e4 * 4);
        __syncthreads();
        As[e4 * 4 + 0][lrow] = av.x; As[e4 * 4 + 1][lrow] = av.y;
        As[e4 * 4 + 2][lrow] = av.z; As[e4 * 4 + 3][lrow] = av.w;
        Bs[e4 * 4 + 0][lrow] = bv.x; Bs[e4 * 4 + 1][lrow] = bv.y;
        Bs[e4 * 4 + 2][lrow] = bv.z; Bs[e4 * 4 + 3][lrow] = bv.w;
        __syncthreads();
        #pragma unroll
        for (int kk = 0; kk < 16; kk++) {
            float4 a = *(const float4*)&As[kk][tx * 4];
            float4 b = *(const float4*)&Bs[kk][ty * 4];
            acc[0][0] = fmaf(a.x, b.x, acc[0][0]); acc[0][1] = fmaf(a.x, b.y, acc[0][1]);
            acc[0][2] = fmaf(a.x, b.z, acc[0][2]); acc[0][3] = fmaf(a.x, b.w, acc[0][3]);
            acc[1][0] = fmaf(a.y, b.x, acc[1][0]); acc[1][1] = fmaf(a.y, b.y, acc[1][1]);
            acc[1][2] = fmaf(a.y, b.z, acc[1][2]); acc[1][3] = fmaf(a.y, b.w, acc[1][3]);
            acc[2][0] = fmaf(a.z, b.x, acc[2][0]); acc[2][1] = fmaf(a.z, b.y, acc[2][1]);
            acc[2][2] = fmaf(a.z, b.z, acc[2][2]); acc[2][3] = fmaf(a.z, b.w, acc[2][3]);
            acc[3][0] = fmaf(a.w, b.x, acc[3][0]); acc[3][1] = fmaf(a.w, b.y, acc[3][1]);
            acc[3][2] = fmaf(a.w, b.z, acc[3][2]); acc[3][3] = fmaf(a.w, b.w, acc[3][3]);
        }
    }

    float4 b4 = *(const float4*)(bias + r0 + ty * 4);
    #pragma unroll
    for (int i = 0; i < 4; i++) {
        int t = t0 + tx * 4 + i;
        float4 o = make_float4(acc[i][0] + b4.x, acc[i][1] + b4.y,
                               acc[i][2] + b4.z, acc[i][3] + b4.w);
        *(float4*)&g_xproj[d][t][r0 + ty * 4] = o;
    }
}

// ===========================================================================
// Kernel 2: persistent bi-LSTM recurrence, 128 co-resident CTAs.
// Exchange: sentinel-validated 16B packets; 16 pollers/CTA x 4 slots each.
// ===========================================================================
__global__ __launch_bounds__(256) void lstm_kernel(
    const float* __restrict__ W_hh_f,
    const float* __restrict__ W_hh_b)
{
    const int tid = threadIdx.x;
    const int bx  = blockIdx.x;
    const int d   = bx >> 6;
    const int cb  = bx & 63;
    const int j0  = cb * JPC;

    const float* __restrict__ Whh = d ? W_hh_b : W_hh_f;

    const int r  = tid >> 3;        // local row 0..31 (= gate*8 + jj)
    const int cg = tid & 7;         // column group (64 cols)
    const int q  = r >> 3;
    const int jj = r & 7;
    const int grow = q * HDIM + j0 + jj;

    const float4* wp = (const float4*)(Whh + (size_t)grow * HDIM + cg * 64);
    float4 w[16];
    #pragma unroll
    for (int i = 0; i < 16; i++) w[i] = wp[i];

    __shared__ float hsm[8 * 68];   // pitched: chunk c at hsm[c*68]
    __shared__ float gacc[32];

    float c = 0.f;

    #pragma unroll 1
    for (int step = 0; step < SEQ; step++) {
        const int t = d ? (SEQ - 1 - step) : step;

        // xp prefetch (warp 0 lanes 0..7); latency hides under poll+GEMV
        float xp0 = 0.f, xp1 = 0.f, xp2 = 0.f, xp3 = 0.f;
        if (tid < 8) {
            const float* xr = &g_xproj[d][t][0];
            xp0 = __ldg(xr + 0 * HDIM + j0 + tid);
            xp1 = __ldg(xr + 1 * HDIM + j0 + tid);
            xp2 = __ldg(xr + 2 * HDIM + j0 + tid);
            xp3 = __ldg(xr + 3 * HDIM + j0 + tid);
        }

        if (step == 0) {
            for (int i = tid; i < 8 * 68; i += 256) hsm[i] = 0.f;
        } else if (tid >= 64 && tid < 80) {
            // 16 pollers: poller p owns slots 4p..4p+3 (h[32p..32p+32)).
            const int p = tid - 64;
            const int tprev = d ? (t + 1) : (t - 1);
            const float4* base = &g_slots[d][tprev][p * 4][0];
            float4 v[8];
            for (;;) {
                #pragma unroll
                for (int i = 0; i < 8; i++) {
                    asm volatile("ld.volatile.global.v4.f32 {%0,%1,%2,%3}, [%4];"
                                 : "=f"(v[i].x), "=f"(v[i].y), "=f"(v[i].z), "=f"(v[i].w)
                                 : "l"(base + i) : "memory");
                }
                bool ok = true;
                #pragma unroll
                for (int i = 0; i < 8; i++)
                    ok &= (__float_as_uint(v[i].x) != SENTINEL_U);
                if (ok) break;
            }
            // slot s = 4p + (i>>1): hsm chunk (s>>3)*68 + (s&7)*8, packet i&1
            #pragma unroll
            for (int i = 0; i < 8; i++) {
                const int s = p * 4 + (i >> 1);
                float* hb = &hsm[(s >> 3) * 68 + (s & 7) * 8 + (i & 1) * 4];
                ((float4*)hb)[0] = v[i];
            }
        }
        __syncthreads();   // S1: hsm ready

        // GEMV slice: row r over cols [cg*64, cg*64+64)
        float a = 0.f;
        const float4* h4 = (const float4*)&hsm[cg * 68];
        #pragma unroll
        for (int i = 0; i < 16; i++) {
            float4 hv = h4[i];
            a = fmaf(w[i].x, hv.x, a);
            a = fmaf(w[i].y, hv.y, a);
            a = fmaf(w[i].z, hv.z, a);
            a = fmaf(w[i].w, hv.w, a);
        }
        a += __shfl_xor_sync(0xffffffffu, a, 4);
        a += __shfl_xor_sync(0xffffffffu, a, 2);
        a += __shfl_xor_sync(0xffffffffu, a, 1);
        if (cg == 0) gacc[r] = a;
        __syncthreads();   // S2: gacc ready (also: hsm reads of this step done)

        // gates on warp 0 lanes 0..7; publish 2 sector-atomic packets
        if (tid < 8) {
            float gi = xp0 + gacc[0 * 8 + tid];
            float gf = xp1 + gacc[1 * 8 + tid];
            float gg = xp2 + gacc[2 * 8 + tid];
            float go = xp3 + gacc[3 * 8 + tid];
            float ig = fast_sigmoid(gi);
            float fg = fast_sigmoid(gf);
            float og = fast_sigmoid(go);
            c = fg * c + ig * fast_tanh(gg);
            float hv = og * fast_tanh(c);

            // lanes 0 and 4 each gather their 4 values and store one packet
            float v0 = __shfl_sync(0xffu, hv, (tid & 4) + 0);
            float v1 = __shfl_sync(0xffu, hv, (tid & 4) + 1);
            float v2 = __shfl_sync(0xffu, hv, (tid & 4) + 2);
            float v3 = __shfl_sync(0xffu, hv, (tid & 4) + 3);
            if ((tid & 3) == 0) {
                float4* slot = &g_slots[d][t][cb][tid >> 2];
                asm volatile("st.relaxed.gpu.global.v4.f32 [%0], {%1,%2,%3,%4};"
                             :: "l"(slot), "f"(v0), "f"(v1), "f"(v2), "f"(v3)
                             : "memory");
            }
        }
        // no trailing barrier: pollers only advance once next-step packets
        // (which require this publish chain) appear.
    }
}

// ===========================================================================
// Kernel 3: per-entity attention pool. Reads h directly from g_slots
// ([d][t] == 512 contiguous floats). entity_seg == repeat(arange(256), 8).
// ===========================================================================
__global__ __launch_bounds__(256) void entity_kernel(
    const float* __restrict__ w_attn,
    const float* __restrict__ b_attn,
    const int*   __restrict__ entity_pos,
    float*       __restrict__ out)
{
    __shared__ int   pos[8];
    __shared__ float ssm[8];
    __shared__ float wsm[8];

    const int e   = blockIdx.x;
    const int tid = threadIdx.x;

    if (tid < 8) pos[tid] = entity_pos[e * KTOK + tid];
    __syncthreads();

    const int warp = tid >> 5, lane = tid & 31;
    const int p = pos[warp];
    const float* h_f = (const float*)&g_slots[0][p][0][0];
    const float* h_b = (const float*)&g_slots[1][p][0][0];
    float a = 0.f;
    for (int cc = lane; cc < HDIM; cc += 32)
        a = fmaf(h_f[cc], w_attn[cc], a);
    for (int cc = lane; cc < HDIM; cc += 32)
        a = fmaf(h_b[cc], w_attn[HDIM + cc], a);
    #pragma unroll
    for (int o = 16; o > 0; o >>= 1) a += __shfl_xor_sync(0xffffffffu, a, o);
    if (lane == 0) ssm[warp] = a + b_attn[0];
    __syncthreads();

    if (tid == 0) {
        float m = ssm[0];
        #pragma unroll
        for (int k = 1; k < 8; k++) m = fmaxf(m, ssm[k]);
        float ex[8], den = 0.f;
        #pragma unroll
        for (int k = 0; k < 8; k++) { ex[k] = expf(ssm[k] - m); den += ex[k]; }
        #pragma unroll
        for (int k = 0; k < 8; k++) wsm[k] = ex[k] / den;
    }
    __syncthreads();

    const int half = tid >> 7;
    const int c4   = tid & 127;
    float4 acc = make_float4(0.f, 0.f, 0.f, 0.f);
    #pragma unroll
    for (int k = 0; k < 8; k++) {
        float wk = wsm[k];
        float4 v = ((const float4*)&g_slots[half][pos[k]][0][0])[c4];
        acc.x = fmaf(wk, v.x, acc.x);
        acc.y = fmaf(wk, v.y, acc.y);
        acc.z = fmaf(wk, v.z, acc.z);
        acc.w = fmaf(wk, v.w, acc.w);
    }
    ((float4*)(out + (size_t)e * (2 * HDIM) + half * HDIM))[c4] = acc;
}

// ===========================================================================
extern "C" void kernel_launch(void* const* d_in, const int* in_sizes, int n_in,
                              void* d_out, int out_size)
{
    const float* emb_table  = (const float*)d_in[0];
    const float* W_ih_f     = (const float*)d_in[1];
    const float* W_hh_f     = (const float*)d_in[2];
    const float* b_f        = (const float*)d_in[3];
    const float* W_ih_b     = (const float*)d_in[4];
    const float* W_hh_b     = (const float*)d_in[5];
    const float* b_b        = (const float*)d_in[6];
    const float* w_attn     = (const float*)d_in[7];
    const float* b_attn     = (const float*)d_in[8];
    const int*   token_ids  = (const int*)d_in[9];
    const int*   entity_pos = (const int*)d_in[10];
    // d_in[11] entity_seg: repeat(arange(NENT), KTOK) -> implicit

    xproj_kernel<<<dim3(32, 32, 2), 256>>>(emb_table, token_ids,
                                           W_ih_f, b_f, W_ih_b, b_b);
    lstm_kernel<<<2 * NCTA, 256>>>(W_hh_f, W_hh_b);
    entity_kernel<<<NENT, 256>>>(w_attn, b_attn, entity_pos, (float*)d_out);
}

// round 7
// speedup vs baseline: 3.1171x; 1.9267x over previous
#include <cuda_runtime.h>
#include <math.h>

#define EMB   512
#define HDIM  512
#define SEQ   2048
#define NENT  256
#define KTOK  8
#define G4H   2048   // 4*HDIM

#define NCTA  64     // CTAs per direction in the recurrence kernel
#define JPC   8      // h-indices owned per CTA (one per warp)

#define SENTINEL_U 0x7F800001u   // NaN pattern; h = o*tanh(c) is never NaN

// ---------------- scratch (device globals; no allocation allowed) ----------
__device__ float g_xproj[2][SEQ][G4H];   // 32 MB: x @ W_ih.T + b
// h history AND exchange medium: plain float array, each 4B store is atomic;
// validity of an element = (bits != SENTINEL_U).
__device__ __align__(16) float g_hx[2][SEQ][HDIM];   // 8 MB

__device__ __forceinline__ float fast_sigmoid(float x) {
    return __fdividef(1.f, 1.f + __expf(-x));
}
__device__ __forceinline__ float fast_tanh(float x) {
    return __fdividef(2.f, 1.f + __expf(-2.f * x)) - 1.f;
}

// ===========================================================================
// Kernel 1: fused embedding gather + x_proj GEMM (+bias), both directions.
// Also sentinel-clears ALL of g_hx (512 blocks x 256 thr x 4 float4 = 2M floats).
// ===========================================================================
__global__ __launch_bounds__(256) void xproj_kernel(
    const float* __restrict__ emb_table,
    const int*   __restrict__ token_ids,
    const float* __restrict__ W_ih_f, const float* __restrict__ b_f,
    const float* __restrict__ W_ih_b, const float* __restrict__ b_b)
{
    __shared__ int   tok[64];
    __shared__ float As[16][68];
    __shared__ float Bs[16][68];

    const int tid = threadIdx.x;
    const int t0  = blockIdx.x * 64;
    const int r0  = blockIdx.y * 64;
    const int d   = blockIdx.z;

    // sentinel-clear the FULL g_hx array (2,097,152 floats = 524,288 float4)
    if (blockIdx.z == 0 && blockIdx.y < 16) {
        const float s = __uint_as_float(SENTINEL_U);
        float4 sv = make_float4(s, s, s, s);
        size_t lin = ((size_t)(blockIdx.y * 32 + blockIdx.x) * 256 + tid) * 4;
        float4* flat = (float4*)&g_hx[0][0][0];
        flat[lin]     = sv;
        flat[lin + 1] = sv;
        flat[lin + 2] = sv;
        flat[lin + 3] = sv;
    }

    if (tid < 64) tok[tid] = token_ids[t0 + tid];
    __syncthreads();

    const float* __restrict__ Wih  = d ? W_ih_b : W_ih_f;
    const float* __restrict__ bias = d ? b_b    : b_f;

    float acc[4][4];
    #pragma unroll
    for (int i = 0; i < 4; i++)
        #pragma unroll
        for (int j = 0; j < 4; j++) acc[i][j] = 0.f;

    const int lrow = tid >> 2;
    const int e4   = tid & 3;
    const int tx   = tid & 15;
    const int ty   = tid >> 4;

    const size_t arow = (size_t)tok[lrow] * EMB;
    const size_t brow = (size_t)(r0 + lrow) * EMB;

    for (int k0 = 0; k0 < EMB; k0 += 16) {
        float4 av = *(const float4*)(emb_table + arow + k0 + e4 * 4);
        float4 bv = *(const float4*)(Wih       + brow + k0 + e4 * 4);
        __syncthreads();
        As[e4 * 4 + 0][lrow] = av.x; As[e4 * 4 + 1][lrow] = av.y;
        As[e4 * 4 + 2][lrow] = av.z; As[e4 * 4 + 3][lrow] = av.w;
        Bs[e4 * 4 + 0][lrow] = bv.x; Bs[e4 * 4 + 1][lrow] = bv.y;
        Bs[e4 * 4 + 2][lrow] = bv.z; Bs[e4 * 4 + 3][lrow] = bv.w;
        __syncthreads();
        #pragma unroll
        for (int kk = 0; kk < 16; kk++) {
            float4 a = *(const float4*)&As[kk][tx * 4];
            float4 b = *(const float4*)&Bs[kk][ty * 4];
            acc[0][0] = fmaf(a.x, b.x, acc[0][0]); acc[0][1] = fmaf(a.x, b.y, acc[0][1]);
            acc[0][2] = fmaf(a.x, b.z, acc[0][2]); acc[0][3] = fmaf(a.x, b.w, acc[0][3]);
            acc[1][0] = fmaf(a.y, b.x, acc[1][0]); acc[1][1] = fmaf(a.y, b.y, acc[1][1]);
            acc[1][2] = fmaf(a.y, b.z, acc[1][2]); acc[1][3] = fmaf(a.y, b.w, acc[1][3]);
            acc[2][0] = fmaf(a.z, b.x, acc[2][0]); acc[2][1] = fmaf(a.z, b.y, acc[2][1]);
            acc[2][2] = fmaf(a.z, b.z, acc[2][2]); acc[2][3] = fmaf(a.z, b.w, acc[2][3]);
            acc[3][0] = fmaf(a.w, b.x, acc[3][0]); acc[3][1] = fmaf(a.w, b.y, acc[3][1]);
            acc[3][2] = fmaf(a.w, b.z, acc[3][2]); acc[3][3] = fmaf(a.w, b.w, acc[3][3]);
        }
    }

    float4 b4 = *(const float4*)(bias + r0 + ty * 4);
    #pragma unroll
    for (int i = 0; i < 4; i++) {
        int t = t0 + tx * 4 + i;
        float4 o = make_float4(acc[i][0] + b4.x, acc[i][1] + b4.y,
                               acc[i][2] + b4.z, acc[i][3] + b4.w);
        *(float4*)&g_xproj[d][t][r0 + ty * 4] = o;
    }
}

// ===========================================================================
// Kernel 2: persistent bi-LSTM recurrence, 128 co-resident CTAs.
// Warp-per-j layout: warp w owns h[j0+w]; lane (q=l>>3, s=l&7) accumulates
// gate q over cols [s*64, s*64+64). After the 8-lane reduce the warp holds
// all 4 gate sums -> lane 0 does gate math and one 4B atomic publish.
// ONE barrier per step; 128 pollers x 1 float4 each.
// ===========================================================================
__global__ __launch_bounds__(256) void lstm_kernel(
    const float* __restrict__ W_hh_f,
    const float* __restrict__ W_hh_b)
{
    const int tid = threadIdx.x;
    const int bx  = blockIdx.x;
    const int d   = bx >> 6;
    const int cb  = bx & 63;
    const int j0  = cb * JPC;

    const float* __restrict__ Whh = d ? W_hh_b : W_hh_f;

    const int w = tid >> 5;         // warp -> local j
    const int l = tid & 31;
    const int q = l >> 3;           // gate 0..3 (i,f,g,o)
    const int s = l & 7;            // 64-col segment
    const int j = j0 + w;
    const int grow = q * HDIM + j;

    const float4* wp = (const float4*)(Whh + (size_t)grow * HDIM + s * 64);
    float4 wr[16];
    #pragma unroll
    for (int i = 0; i < 16; i++) wr[i] = wp[i];

    __shared__ float hsm[8 * 68];   // pitched: col-chunk c at hsm[c*68]
    float c = 0.f;                  // cell state, live in lane 0 of each warp

    #pragma unroll 1
    for (int step = 0; step < SEQ; step++) {
        const int t = d ? (SEQ - 1 - step) : step;

        // xp: lanes s==0 (l = 0,8,16,24) load gate q's input for this j
        float xp = 0.f;
        if (s == 0) xp = __ldg(&g_xproj[d][t][q * HDIM + j]);

        if (step == 0) {
            for (int i = tid; i < 8 * 68; i += 256) hsm[i] = 0.f;
        } else if (tid < 128) {
            // 128 pollers, one float4 each: poll == data delivery
            const int tprev = d ? (t + 1) : (t - 1);
            const float* src = &g_hx[d][tprev][tid * 4];
            float4 v;
            for (;;) {
                asm volatile("ld.volatile.global.v4.f32 {%0,%1,%2,%3}, [%4];"
                             : "=f"(v.x), "=f"(v.y), "=f"(v.z), "=f"(v.w)
                             : "l"(src) : "memory");
                if (__float_as_uint(v.x) != SENTINEL_U &&
                    __float_as_uint(v.y) != SENTINEL_U &&
                    __float_as_uint(v.z) != SENTINEL_U &&
                    __float_as_uint(v.w) != SENTINEL_U) break;
            }
            *(float4*)&hsm[(tid >> 4) * 68 + ((tid * 4) & 63)] = v;
        }
        __syncthreads();   // the ONLY barrier per step

        // GEMV: 64 MACs per lane over its segment
        float a = 0.f;
        const float4* h4 = (const float4*)&hsm[s * 68];
        #pragma unroll
        for (int i = 0; i < 16; i++) {
            float4 hv = h4[i];
            a = fmaf(wr[i].x, hv.x, a);
            a = fmaf(wr[i].y, hv.y, a);
            a = fmaf(wr[i].z, hv.z, a);
            a = fmaf(wr[i].w, hv.w, a);
        }
        a += __shfl_xor_sync(0xffffffffu, a, 4);
        a += __shfl_xor_sync(0xffffffffu, a, 2);
        a += __shfl_xor_sync(0xffffffffu, a, 1);
        a += xp;   // complete gate value on lanes s==0

        // gather the 4 gates into lane 0
        float gi = __shfl_sync(0xffffffffu, a, 0);
        float gf = __shfl_sync(0xffffffffu, a, 8);
        float gg = __shfl_sync(0xffffffffu, a, 16);
        float go = __shfl_sync(0xffffffffu, a, 24);

        if (l == 0) {
            float ig = fast_sigmoid(gi);
            float fg = fast_sigmoid(gf);
            float og = fast_sigmoid(go);
            c = fg * c + ig * fast_tanh(gg);
            float hv = og * fast_tanh(c);
            asm volatile("st.relaxed.gpu.global.f32 [%0], %1;"
                         :: "l"(&g_hx[d][t][j]), "f"(hv) : "memory");
        }
        // no trailing barrier: next-step hsm overwrites are gated by the
        // pollers' success, which requires every warp's publish (and hence
        // every warp's hsm reads) of this step.
    }
}

// ===========================================================================
// Kernel 3: per-entity attention pool (entity_seg == repeat(arange(256), 8)).
// ===========================================================================
__global__ __launch_bounds__(256) void entity_kernel(
    const float* __restrict__ w_attn,
    const float* __restrict__ b_attn,
    const int*   __restrict__ entity_pos,
    float*       __restrict__ out)
{
    __shared__ int   pos[8];
    __shared__ float ssm[8];
    __shared__ float wsm[8];

    const int e   = blockIdx.x;
    const int tid = threadIdx.x;

    if (tid < 8) pos[tid] = entity_pos[e * KTOK + tid];
    __syncthreads();

    const int warp = tid >> 5, lane = tid & 31;
    const int p = pos[warp];
    float a = 0.f;
    for (int cc = lane; cc < HDIM; cc += 32)
        a = fmaf(g_hx[0][p][cc], w_attn[cc], a);
    for (int cc = lane; cc < HDIM; cc += 32)
        a = fmaf(g_hx[1][p][cc], w_attn[HDIM + cc], a);
    #pragma unroll
    for (int o = 16; o > 0; o >>= 1) a += __shfl_xor_sync(0xffffffffu, a, o);
    if (lane == 0) ssm[warp] = a + b_attn[0];
    __syncthreads();

    if (tid == 0) {
        float m = ssm[0];
        #pragma unroll
        for (int k = 1; k < 8; k++) m = fmaxf(m, ssm[k]);
        float ex[8], den = 0.f;
        #pragma unroll
        for (int k = 0; k < 8; k++) { ex[k] = expf(ssm[k] - m); den += ex[k]; }
        #pragma unroll
        for (int k = 0; k < 8; k++) wsm[k] = ex[k] / den;
    }
    __syncthreads();

    const int half = tid >> 7;
    const int c4   = tid & 127;
    float4 acc = make_float4(0.f, 0.f, 0.f, 0.f);
    #pragma unroll
    for (int k = 0; k < 8; k++) {
        float wk = wsm[k];
        float4 v = ((const float4*)&g_hx[half][pos[k]][0])[c4];
        acc.x = fmaf(wk, v.x, acc.x);
        acc.y = fmaf(wk, v.y, acc.y);
        acc.z = fmaf(wk, v.z, acc.z);
        acc.w = fmaf(wk, v.w, acc.w);
    }
    ((float4*)(out + (size_t)e * (2 * HDIM) + half * HDIM))[c4] = acc;
}

// ===========================================================================
extern "C" void kernel_launch(void* const* d_in, const int* in_sizes, int n_in,
                              void* d_out, int out_size)
{
    const float* emb_table  = (const float*)d_in[0];
    const float* W_ih_f     = (const float*)d_in[1];
    const float* W_hh_f     = (const float*)d_in[2];
    const float* b_f        = (const float*)d_in[3];
    const float* W_ih_b     = (const float*)d_in[4];
    const float* W_hh_b     = (const float*)d_in[5];
    const float* b_b        = (const float*)d_in[6];
    const float* w_attn     = (const float*)d_in[7];
    const float* b_attn     = (const float*)d_in[8];
    const int*   token_ids  = (const int*)d_in[9];
    const int*   entity_pos = (const int*)d_in[10];
    // d_in[11] entity_seg: repeat(arange(NENT), KTOK) -> implicit

    xproj_kernel<<<dim3(32, 32, 2), 256>>>(emb_table, token_ids,
                                           W_ih_f, b_f, W_ih_b, b_b);
    lstm_kernel<<<2 * NCTA, 256>>>(W_hh_f, W_hh_b);
    entity_kernel<<<NENT, 256>>>(w_attn, b_attn, entity_pos, (float*)d_out);
}

// round 9
// speedup vs baseline: 3.1547x; 1.0121x over previous
#include <cuda_runtime.h>
#include <math.h>

#define EMB   512
#define HDIM  512
#define SEQ   2048
#define NENT  256
#define KTOK  8
#define G4H   2048   // 4*HDIM

#define NCTA  64     // CTAs per direction in the recurrence kernel
#define JPC   8      // h-indices owned per CTA (one per warp)

#define SENTINEL_U 0x7F800001u   // NaN pattern; h = o*tanh(c) is never NaN

// ---------------- scratch (device globals; no allocation allowed) ----------
__device__ float g_xproj[2][SEQ][G4H];   // 32 MB: x @ W_ih.T + b
// h history AND exchange medium: plain float array, each 4B store is atomic;
// validity of an element = (bits != SENTINEL_U).
__device__ __align__(16) float g_hx[2][SEQ][HDIM];   // 8 MB

__device__ __forceinline__ float fast_sigmoid(float x) {
    return __fdividef(1.f, 1.f + __expf(-x));
}
__device__ __forceinline__ float fast_tanh(float x) {
    return __fdividef(2.f, 1.f + __expf(-2.f * x)) - 1.f;
}

// ===========================================================================
// Kernel 1: fused embedding gather + x_proj GEMM (+bias), both directions.
// Also sentinel-clears ALL of g_hx.
// ===========================================================================
__global__ __launch_bounds__(256) void xproj_kernel(
    const float* __restrict__ emb_table,
    const int*   __restrict__ token_ids,
    const float* __restrict__ W_ih_f, const float* __restrict__ b_f,
    const float* __restrict__ W_ih_b, const float* __restrict__ b_b)
{
    __shared__ int   tok[64];
    __shared__ float As[16][68];
    __shared__ float Bs[16][68];

    const int tid = threadIdx.x;
    const int t0  = blockIdx.x * 64;
    const int r0  = blockIdx.y * 64;
    const int d   = blockIdx.z;

    // sentinel-clear the FULL g_hx array (2,097,152 floats = 524,288 float4)
    if (blockIdx.z == 0 && blockIdx.y < 16) {
        const float s = __uint_as_float(SENTINEL_U);
        float4 sv = make_float4(s, s, s, s);
        size_t lin = ((size_t)(blockIdx.y * 32 + blockIdx.x) * 256 + tid) * 4;
        float4* flat = (float4*)&g_hx[0][0][0];
        flat[lin]     = sv;
        flat[lin + 1] = sv;
        flat[lin + 2] = sv;
        flat[lin + 3] = sv;
    }

    if (tid < 64) tok[tid] = token_ids[t0 + tid];
    __syncthreads();

    const float* __restrict__ Wih  = d ? W_ih_b : W_ih_f;
    const float* __restrict__ bias = d ? b_b    : b_f;

    float acc[4][4];
    #pragma unroll
    for (int i = 0; i < 4; i++)
        #pragma unroll
        for (int j = 0; j < 4; j++) acc[i][j] = 0.f;

    const int lrow = tid >> 2;
    const int e4   = tid & 3;
    const int tx   = tid & 15;
    const int ty   = tid >> 4;

    const size_t arow = (size_t)tok[lrow] * EMB;
    const size_t brow = (size_t)(r0 + lrow) * EMB;

    for (int k0 = 0; k0 < EMB; k0 += 16) {
        float4 av = *(const float4*)(emb_table + arow + k0 + e4 * 4);
        float4 bv = *(const float4*)(Wih       + brow + k0 + e4 * 4);
        __syncthreads();
        As[e4 * 4 + 0][lrow] = av.x; As[e4 * 4 + 1][lrow] = av.y;
        As[e4 * 4 + 2][lrow] = av.z; As[e4 * 4 + 3][lrow] = av.w;
        Bs[e4 * 4 + 0][lrow] = bv.x; Bs[e4 * 4 + 1][lrow] = bv.y;
        Bs[e4 * 4 + 2][lrow] = bv.z; Bs[e4 * 4 + 3][lrow] = bv.w;
        __syncthreads();
        #pragma unroll
        for (int kk = 0; kk < 16; kk++) {
            float4 a = *(const float4*)&As[kk][tx * 4];
            float4 b = *(const float4*)&Bs[kk][ty * 4];
            acc[0][0] = fmaf(a.x, b.x, acc[0][0]); acc[0][1] = fmaf(a.x, b.y, acc[0][1]);
            acc[0][2] = fmaf(a.x, b.z, acc[0][2]); acc[0][3] = fmaf(a.x, b.w, acc[0][3]);
            acc[1][0] = fmaf(a.y, b.x, acc[1][0]); acc[1][1] = fmaf(a.y, b.y, acc[1][1]);
            acc[1][2] = fmaf(a.y, b.z, acc[1][2]); acc[1][3] = fmaf(a.y, b.w, acc[1][3]);
            acc[2][0] = fmaf(a.z, b.x, acc[2][0]); acc[2][1] = fmaf(a.z, b.y, acc[2][1]);
            acc[2][2] = fmaf(a.z, b.z, acc[2][2]); acc[2][3] = fmaf(a.z, b.w, acc[2][3]);
            acc[3][0] = fmaf(a.w, b.x, acc[3][0]); acc[3][1] = fmaf(a.w, b.y, acc[3][1]);
            acc[3][2] = fmaf(a.w, b.z, acc[3][2]); acc[3][3] = fmaf(a.w, b.w, acc[3][3]);
        }
    }

    float4 b4 = *(const float4*)(bias + r0 + ty * 4);
    #pragma unroll
    for (int i = 0; i < 4; i++) {
        int t = t0 + tx * 4 + i;
        float4 o = make_float4(acc[i][0] + b4.x, acc[i][1] + b4.y,
                               acc[i][2] + b4.z, acc[i][3] + b4.w);
        *(float4*)&g_xproj[d][t][r0 + ty * 4] = o;
    }
}

// ===========================================================================
// Kernel 2: persistent bi-LSTM recurrence, 128 co-resident CTAs.
// Warp-per-j; GEMV in fma.rn.f32x2 (2 fp32 MACs/instr, 2 indep chains);
// activations computed in parallel on lanes 0/8/16/24; one barrier/step.
// ===========================================================================
__global__ __launch_bounds__(256) void lstm_kernel(
    const float* __restrict__ W_hh_f,
    const float* __restrict__ W_hh_b)
{
    const int tid = threadIdx.x;
    const int bx  = blockIdx.x;
    const int d   = bx >> 6;
    const int cb  = bx & 63;
    const int j0  = cb * JPC;

    const float* __restrict__ Whh = d ? W_hh_b : W_hh_f;

    const int w = tid >> 5;         // warp -> local j
    const int l = tid & 31;
    const int q = l >> 3;           // gate 0..3 (i,f,g,o)
    const int s = l & 7;            // 64-col segment
    const int j = j0 + w;
    const int grow = q * HDIM + j;

    // weights packed as f32x2 pairs: 16 x ulonglong2 = 64 floats
    const ulonglong2* wp = (const ulonglong2*)(Whh + (size_t)grow * HDIM + s * 64);
    ulonglong2 wr[16];
    #pragma unroll
    for (int i = 0; i < 16; i++) wr[i] = wp[i];

    __shared__ float hsm[8 * 68];   // pitched: col-chunk c at hsm[c*68] (272B, 16B-aligned)
    float c = 0.f;                  // cell state, live in lane 0 of each warp

    #pragma unroll 1
    for (int step = 0; step < SEQ; step++) {
        const int t = d ? (SEQ - 1 - step) : step;

        // xp: lanes s==0 (l = 0,8,16,24) load gate q's input for this j
        float xp = 0.f;
        if (s == 0) xp = __ldg(&g_xproj[d][t][q * HDIM + j]);

        if (step == 0) {
            for (int i = tid; i < 8 * 68; i += 256) hsm[i] = 0.f;
        } else if (tid < 128) {
            // 128 pollers, one float4 each: poll == data delivery
            const int tprev = d ? (t + 1) : (t - 1);
            const float* src = &g_hx[d][tprev][tid * 4];
            float4 v;
            for (;;) {
                asm volatile("ld.volatile.global.v4.f32 {%0,%1,%2,%3}, [%4];"
                             : "=f"(v.x), "=f"(v.y), "=f"(v.z), "=f"(v.w)
                             : "l"(src) : "memory");
                if (__float_as_uint(v.x) != SENTINEL_U &&
                    __float_as_uint(v.y) != SENTINEL_U &&
                    __float_as_uint(v.z) != SENTINEL_U &&
                    __float_as_uint(v.w) != SENTINEL_U) break;
            }
            *(float4*)&hsm[(tid >> 4) * 68 + ((tid * 4) & 63)] = v;
        }
        __syncthreads();   // the ONLY barrier per step

        // GEMV: 64 MACs per lane as 32 packed f32x2 FMAs, 2 indep chains
        unsigned long long acc0 = 0ull, acc1 = 0ull;
        const ulonglong2* h2 = (const ulonglong2*)&hsm[s * 68];
        #pragma unroll
        for (int i = 0; i < 16; i++) {
            ulonglong2 hv = h2[i];
            asm("fma.rn.f32x2 %0, %1, %2, %0;"
                : "+l"(acc0) : "l"(wr[i].x), "l"(hv.x));
            asm("fma.rn.f32x2 %0, %1, %2, %0;"
                : "+l"(acc1) : "l"(wr[i].y), "l"(hv.y));
        }
        float lo0, hi0, lo1, hi1;
        asm("mov.b64 {%0,%1}, %2;" : "=f"(lo0), "=f"(hi0) : "l"(acc0));
        asm("mov.b64 {%0,%1}, %2;" : "=f"(lo1), "=f"(hi1) : "l"(acc1));
        float a = (lo0 + hi0) + (lo1 + hi1);

        // reduce across the 8 segments (aligned 8-lane subsets)
        a += __shfl_xor_sync(0xffffffffu, a, 4);
        a += __shfl_xor_sync(0xffffffffu, a, 2);
        a += __shfl_xor_sync(0xffffffffu, a, 1);
        a += xp;   // full gate value on lanes s==0 (l = 0,8,16,24)

        // parallel activations: lane 0->sigmoid(gi), 8->sigmoid(gf),
        // 16->tanh(gg) via 2*sigmoid(2x)-1, 24->sigmoid(go). Branchless.
        float arg = (q == 2) ? 2.f * a : a;
        float sg  = fast_sigmoid(arg);
        float act = (q == 2) ? 2.f * sg - 1.f : sg;

        float ig = __shfl_sync(0xffffffffu, act, 0);
        float fg = __shfl_sync(0xffffffffu, act, 8);
        float tg = __shfl_sync(0xffffffffu, act, 16);
        float og = __shfl_sync(0xffffffffu, act, 24);

        if (l == 0) {
            c = fg * c + ig * tg;
            float hv = og * fast_tanh(c);
            asm volatile("st.relaxed.gpu.global.f32 [%0], %1;"
                         :: "l"(&g_hx[d][t][j]), "f"(hv) : "memory");
        }
        // no trailing barrier: next-step hsm overwrites are gated by the
        // pollers' success, which requires every warp's publish (and hence
        // every warp's hsm reads) of this step.
    }
}

// ===========================================================================
// Kernel 3: per-entity attention pool (entity_seg == repeat(arange(256), 8)).
// ===========================================================================
__global__ __launch_bounds__(256) void entity_kernel(
    const float* __restrict__ w_attn,
    const float* __restrict__ b_attn,
    const int*   __restrict__ entity_pos,
    float*       __restrict__ out)
{
    __shared__ int   pos[8];
    __shared__ float ssm[8];
    __shared__ float wsm[8];

    const int e   = blockIdx.x;
    const int tid = threadIdx.x;

    if (tid < 8) pos[tid] = entity_pos[e * KTOK + tid];
    __syncthreads();

    const int warp = tid >> 5, lane = tid & 31;
    const int p = pos[warp];
    float a = 0.f;
    for (int cc = lane; cc < HDIM; cc += 32)
        a = fmaf(g_hx[0][p][cc], w_attn[cc], a);
    for (int cc = lane; cc < HDIM; cc += 32)
        a = fmaf(g_hx[1][p][cc], w_attn[HDIM + cc], a);
    #pragma unroll
    for (int o = 16; o > 0; o >>= 1) a += __shfl_xor_sync(0xffffffffu, a, o);
    if (lane == 0) ssm[warp] = a + b_attn[0];
    __syncthreads();

    if (tid == 0) {
        float m = ssm[0];
        #pragma unroll
        for (int k = 1; k < 8; k++) m = fmaxf(m, ssm[k]);
        float ex[8], den = 0.f;
        #pragma unroll
        for (int k = 0; k < 8; k++) { ex[k] = expf(ssm[k] - m); den += ex[k]; }
        #pragma unroll
        for (int k = 0; k < 8; k++) wsm[k] = ex[k] / den;
    }
    __syncthreads();

    const int half = tid >> 7;
    const int c4   = tid & 127;
    float4 acc = make_float4(0.f, 0.f, 0.f, 0.f);
    #pragma unroll
    for (int k = 0; k < 8; k++) {
        float wk = wsm[k];
        float4 v = ((const float4*)&g_hx[half][pos[k]][0])[c4];
        acc.x = fmaf(wk, v.x, acc.x);
        acc.y = fmaf(wk, v.y, acc.y);
        acc.z = fmaf(wk, v.z, acc.z);
        acc.w = fmaf(wk, v.w, acc.w);
    }
    ((float4*)(out + (size_t)e * (2 * HDIM) + half * HDIM))[c4] = acc;
}

// ===========================================================================
extern "C" void kernel_launch(void* const* d_in, const int* in_sizes, int n_in,
                              void* d_out, int out_size)
{
    const float* emb_table  = (const float*)d_in[0];
    const float* W_ih_f     = (const float*)d_in[1];
    const float* W_hh_f     = (const float*)d_in[2];
    const float* b_f        = (const float*)d_in[3];
    const float* W_ih_b     = (const float*)d_in[4];
    const float* W_hh_b     = (const float*)d_in[5];
    const float* b_b        = (const float*)d_in[6];
    const float* w_attn     = (const float*)d_in[7];
    const float* b_attn     = (const float*)d_in[8];
    const int*   token_ids  = (const int*)d_in[9];
    const int*   entity_pos = (const int*)d_in[10];
    // d_in[11] entity_seg: repeat(arange(NENT), KTOK) -> implicit

    xproj_kernel<<<dim3(32, 32, 2), 256>>>(emb_table, token_ids,
                                           W_ih_f, b_f, W_ih_b, b_b);
    lstm_kernel<<<2 * NCTA, 256>>>(W_hh_f, W_hh_b);
    entity_kernel<<<NENT, 256>>>(w_attn, b_attn, entity_pos, (float*)d_out);
}